// round 11
// baseline (speedup 1.0000x reference)
#include <cuda_runtime.h>
#include <cuda_bf16.h>
#include <cstddef>

// MultiNetworkRNN: N_NET=32, N_UNITS=2048, N_EXC=1638, N_INH=410
// out[n,q] = r + DT*((relu(total)-r)/TAU)
// total[:,0:NE]  = r_e @ W_ee + r_i @ W_ie + unit_input_e
// total[:,NE:NU] = r_e @ W_ei + r_i @ W_ii + unit_input_i + inter
// inter[i,a] = sum_{j,b} W_inter[i,j,a,b] * r[i, NE+b]
//
// R11: R10 (best: 180.3us) + reduce-kernel polish: __ldcs on read-once
// streams (g_partial, unit_input) and float2-vectorized epilogue.

#define N_NET 32
#define NU 2048
#define NE 1638
#define NI 410
#define DT 0.01f
#define TAU 0.1f

#define P_SLICES 16
#define P_PER_SLICE (NU / P_SLICES)             // 128

#define PARTIAL_BLOCKS (16 * P_SLICES * N_NET)  // 8192
#define INTER_BLOCKS (N_NET * NI)               // 13120
#define TOTAL_BLOCKS (PARTIAL_BLOCKS + INTER_BLOCKS)  // 21312

__device__ float g_inter[N_NET * NI];
__device__ float g_partial[P_SLICES * N_NET * NU];   // [slice][net][q], 4 MB

// ---------------------------------------------------------------------------
// Fused streaming kernel (unchanged from R10 — at the measured roofline):
//   blocks [0, PARTIAL_BLOCKS)          : partial GEMV sums (longer blocks)
//   blocks [PARTIAL_BLOCKS, TOTAL)      : inter[i,a]       (shorter blocks)
// ---------------------------------------------------------------------------
__global__ void __launch_bounds__(128) fused_kernel(
    const float* __restrict__ r,
    const float* __restrict__ W_ee,
    const float* __restrict__ W_ei,
    const float* __restrict__ W_ie,
    const float* __restrict__ W_ii,
    const float* __restrict__ W_inter)
{
    __shared__ float rs[NI + 8];
    __shared__ float red[4];

    const int bx  = blockIdx.x;
    const int tid = threadIdx.x;

    if (bx >= PARTIAL_BLOCKS) {
        // ----------------- inter role -----------------
        const int bi = bx - PARTIAL_BLOCKS;
        const int a = bi % NI;
        const int i = bi / NI;

        const float* ri = r + (size_t)i * NU + NE;
        for (int b = tid; b < NI; b += 128) rs[b] = ri[b];
        __syncthreads();

        const float* base = W_inter + (size_t)i * N_NET * (NI * NI) + (size_t)a * NI;

        float acc = 0.f;
        for (int t = tid; t < NI / 2; t += 128) {
            const float x = rs[2 * t];
            const float y = rs[2 * t + 1];
            #pragma unroll 8
            for (int j = 0; j < N_NET; ++j) {
                const float2 w = __ldcs((const float2*)(base + (size_t)j * (NI * NI) + 2 * t));
                acc = fmaf(w.x, x, acc);
                acc = fmaf(w.y, y, acc);
            }
        }

        #pragma unroll
        for (int o = 16; o > 0; o >>= 1)
            acc += __shfl_down_sync(0xFFFFFFFFu, acc, o);
        if ((tid & 31) == 0) red[tid >> 5] = acc;
        __syncthreads();
        if (tid == 0)
            g_inter[i * NI + a] = red[0] + red[1] + red[2] + red[3];
    } else {
        // ----------------- partial GEMV role -----------------
        const int qt  = bx & 15;                    // q tile (16)
        const int ps  = (bx >> 4) & (P_SLICES - 1); // p slice (16)
        const int n   = bx >> 8;                    // net (32)

        const int q  = qt * 128 + tid;     // 0..2047
        const int pa = ps * P_PER_SLICE;
        const int pb = pa + P_PER_SLICE;

        rs[tid] = r[(size_t)n * NU + pa + tid];
        __syncthreads();

        const float* colE;
        const float* colI;
        int stride;
        if (q < NE) {
            stride = NE;
            colE = W_ee + (size_t)n * NE * NE + q;
            colI = W_ie + (size_t)n * NI * NE + q;
        } else {
            const int qq = q - NE;
            stride = NI;
            colE = W_ei + (size_t)n * NE * NI + qq;
            colI = W_ii + (size_t)n * NI * NI + qq;
        }

        float acc = 0.f;

        // rows p in [pa, min(pb, NE)) from the E-row matrix
        {
            const int pe = (pb < NE) ? pb : NE;
            int p = pa;
            for (; p + 8 <= pe; p += 8) {
                const float w0 = __ldcs(colE + (size_t)(p + 0) * stride);
                const float w1 = __ldcs(colE + (size_t)(p + 1) * stride);
                const float w2 = __ldcs(colE + (size_t)(p + 2) * stride);
                const float w3 = __ldcs(colE + (size_t)(p + 3) * stride);
                const float w4 = __ldcs(colE + (size_t)(p + 4) * stride);
                const float w5 = __ldcs(colE + (size_t)(p + 5) * stride);
                const float w6 = __ldcs(colE + (size_t)(p + 6) * stride);
                const float w7 = __ldcs(colE + (size_t)(p + 7) * stride);
                const int t = p - pa;
                acc = fmaf(w0, rs[t + 0], acc);
                acc = fmaf(w1, rs[t + 1], acc);
                acc = fmaf(w2, rs[t + 2], acc);
                acc = fmaf(w3, rs[t + 3], acc);
                acc = fmaf(w4, rs[t + 4], acc);
                acc = fmaf(w5, rs[t + 5], acc);
                acc = fmaf(w6, rs[t + 6], acc);
                acc = fmaf(w7, rs[t + 7], acc);
            }
            for (; p < pe; ++p)
                acc = fmaf(__ldcs(colE + (size_t)p * stride), rs[p - pa], acc);
        }

        // rows p in [max(pa, NE), pb) from the I-row matrix
        {
            const int p0 = (pa > NE) ? pa : NE;
            int p = p0;
            for (; p + 8 <= pb; p += 8) {
                const float w0 = __ldcs(colI + (size_t)(p - NE + 0) * stride);
                const float w1 = __ldcs(colI + (size_t)(p - NE + 1) * stride);
                const float w2 = __ldcs(colI + (size_t)(p - NE + 2) * stride);
                const float w3 = __ldcs(colI + (size_t)(p - NE + 3) * stride);
                const float w4 = __ldcs(colI + (size_t)(p - NE + 4) * stride);
                const float w5 = __ldcs(colI + (size_t)(p - NE + 5) * stride);
                const float w6 = __ldcs(colI + (size_t)(p - NE + 6) * stride);
                const float w7 = __ldcs(colI + (size_t)(p - NE + 7) * stride);
                const int t = p - pa;
                acc = fmaf(w0, rs[t + 0], acc);
                acc = fmaf(w1, rs[t + 1], acc);
                acc = fmaf(w2, rs[t + 2], acc);
                acc = fmaf(w3, rs[t + 3], acc);
                acc = fmaf(w4, rs[t + 4], acc);
                acc = fmaf(w5, rs[t + 5], acc);
                acc = fmaf(w6, rs[t + 6], acc);
                acc = fmaf(w7, rs[t + 7], acc);
            }
            for (; p < pb; ++p)
                acc = fmaf(__ldcs(colI + (size_t)(p - NE) * stride), rs[p - pa], acc);
        }

        g_partial[((size_t)ps * N_NET + n) * NU + q] = acc;
    }

#if __CUDA_ARCH__ >= 900
    cudaTriggerProgrammaticLaunchCompletion();
#endif
}

// ---------------------------------------------------------------------------
// Reduce 16 partials + unit_input (+inter for inhibitory) + epilogue.
// PDL-launched; float2-vectorized (q-pairs; NE even so no pair straddles the
// exc/inh boundary); __ldcs on read-once streams.
// ---------------------------------------------------------------------------
__global__ void __launch_bounds__(1024) reduce_kernel(
    const float* __restrict__ unit_input,
    const float* __restrict__ r,
    float* __restrict__ out)
{
    const int pidx = blockIdx.x * 1024 + threadIdx.x;  // pair index, 0..32767
    const int idx  = pidx * 2;
    const int n = idx >> 11;
    const int q = idx & 2047;

    // prefetch (independent of primary kernel's output)
    const float2 ui = __ldcs((const float2*)(unit_input + idx));
    const float2 rv = *(const float2*)(r + idx);

#if __CUDA_ARCH__ >= 900
    cudaGridDependencySynchronize();
#endif

    float a0 = 0.f, a1 = 0.f;
    #pragma unroll
    for (int s = 0; s < P_SLICES; ++s) {
        const float2 pp = __ldcs((const float2*)(g_partial + ((size_t)s * N_NET + n) * NU + q));
        a0 += pp.x;
        a1 += pp.y;
    }

    a0 += ui.x;
    a1 += ui.y;
    if (q >= NE) {
        a0 += g_inter[n * NI + (q - NE)];
        a1 += g_inter[n * NI + (q - NE) + 1];
    }

    float2 o;
    const float phi0 = fmaxf(a0, 0.f);
    const float phi1 = fmaxf(a1, 0.f);
    o.x = rv.x + DT * ((phi0 - rv.x) / TAU);
    o.y = rv.y + DT * ((phi1 - rv.y) / TAU);
    *(float2*)(out + idx) = o;
}

extern "C" void kernel_launch(void* const* d_in, const int* in_sizes, int n_in,
                              void* d_out, int out_size)
{
    const float* unit_input = (const float*)d_in[0];
    const float* r          = (const float*)d_in[1];
    const float* W_ee       = (const float*)d_in[2];
    const float* W_ei       = (const float*)d_in[3];
    const float* W_ie       = (const float*)d_in[4];
    const float* W_ii       = (const float*)d_in[5];
    const float* W_inter    = (const float*)d_in[6];
    float* out = (float*)d_out;

    fused_kernel<<<TOTAL_BLOCKS, 128>>>(r, W_ee, W_ei, W_ie, W_ii, W_inter);

    cudaLaunchConfig_t cfg = {};
    cfg.gridDim  = dim3(32, 1, 1);
    cfg.blockDim = dim3(1024, 1, 1);
    cfg.dynamicSmemBytes = 0;
    cfg.stream = 0;
    cudaLaunchAttribute attrs[1];
    attrs[0].id = cudaLaunchAttributeProgrammaticStreamSerialization;
    attrs[0].val.programmaticStreamSerializationAllowed = 1;
    cfg.attrs = attrs;
    cfg.numAttrs = 1;
    cudaLaunchKernelEx(&cfg, reduce_kernel, unit_input, r, out);
}

// round 12
// speedup vs baseline: 1.0244x; 1.0244x over previous
#include <cuda_runtime.h>
#include <cuda_bf16.h>
#include <cstddef>

// MultiNetworkRNN: N_NET=32, N_UNITS=2048, N_EXC=1638, N_INH=410
// out[n,q] = r + DT*((relu(total)-r)/TAU)
// total[:,0:NE]  = r_e @ W_ee + r_i @ W_ie + unit_input_e
// total[:,NE:NU] = r_e @ W_ei + r_i @ W_ii + unit_input_i + inter
// inter[i,a] = sum_{j,b} W_inter[i,j,a,b] * r[i, NE+b]
//
// FINAL (= R10, best measured 180.3us @ ~7.0 TB/s effective):
//  - fused streaming kernel: partial GEMVs (LPT-first) + inter blocks,
//    8-deep load batching, __ldcs on all read-once weight streams
//  - PDL-overlapped reduce/epilogue kernel

#define N_NET 32
#define NU 2048
#define NE 1638
#define NI 410
#define DT 0.01f
#define TAU 0.1f

#define P_SLICES 16
#define P_PER_SLICE (NU / P_SLICES)             // 128

#define PARTIAL_BLOCKS (16 * P_SLICES * N_NET)  // 8192
#define INTER_BLOCKS (N_NET * NI)               // 13120
#define TOTAL_BLOCKS (PARTIAL_BLOCKS + INTER_BLOCKS)  // 21312

__device__ float g_inter[N_NET * NI];
__device__ float g_partial[P_SLICES * N_NET * NU];   // [slice][net][q], 4 MB

// ---------------------------------------------------------------------------
// Fused streaming kernel:
//   blocks [0, PARTIAL_BLOCKS)          : partial GEMV sums (longer blocks)
//   blocks [PARTIAL_BLOCKS, TOTAL)      : inter[i,a]       (shorter blocks)
// ---------------------------------------------------------------------------
__global__ void __launch_bounds__(128) fused_kernel(
    const float* __restrict__ r,
    const float* __restrict__ W_ee,
    const float* __restrict__ W_ei,
    const float* __restrict__ W_ie,
    const float* __restrict__ W_ii,
    const float* __restrict__ W_inter)
{
    __shared__ float rs[NI + 8];
    __shared__ float red[4];

    const int bx  = blockIdx.x;
    const int tid = threadIdx.x;

    if (bx >= PARTIAL_BLOCKS) {
        // ----------------- inter role -----------------
        const int bi = bx - PARTIAL_BLOCKS;
        const int a = bi % NI;
        const int i = bi / NI;

        const float* ri = r + (size_t)i * NU + NE;
        for (int b = tid; b < NI; b += 128) rs[b] = ri[b];
        __syncthreads();

        const float* base = W_inter + (size_t)i * N_NET * (NI * NI) + (size_t)a * NI;

        float acc = 0.f;
        for (int t = tid; t < NI / 2; t += 128) {
            const float x = rs[2 * t];
            const float y = rs[2 * t + 1];
            #pragma unroll 8
            for (int j = 0; j < N_NET; ++j) {
                const float2 w = __ldcs((const float2*)(base + (size_t)j * (NI * NI) + 2 * t));
                acc = fmaf(w.x, x, acc);
                acc = fmaf(w.y, y, acc);
            }
        }

        #pragma unroll
        for (int o = 16; o > 0; o >>= 1)
            acc += __shfl_down_sync(0xFFFFFFFFu, acc, o);
        if ((tid & 31) == 0) red[tid >> 5] = acc;
        __syncthreads();
        if (tid == 0)
            g_inter[i * NI + a] = red[0] + red[1] + red[2] + red[3];
    } else {
        // ----------------- partial GEMV role -----------------
        const int qt  = bx & 15;                    // q tile (16)
        const int ps  = (bx >> 4) & (P_SLICES - 1); // p slice (16)
        const int n   = bx >> 8;                    // net (32)

        const int q  = qt * 128 + tid;     // 0..2047
        const int pa = ps * P_PER_SLICE;
        const int pb = pa + P_PER_SLICE;

        rs[tid] = r[(size_t)n * NU + pa + tid];
        __syncthreads();

        const float* colE;
        const float* colI;
        int stride;
        if (q < NE) {
            stride = NE;
            colE = W_ee + (size_t)n * NE * NE + q;
            colI = W_ie + (size_t)n * NI * NE + q;
        } else {
            const int qq = q - NE;
            stride = NI;
            colE = W_ei + (size_t)n * NE * NI + qq;
            colI = W_ii + (size_t)n * NI * NI + qq;
        }

        float acc = 0.f;

        // rows p in [pa, min(pb, NE)) from the E-row matrix
        {
            const int pe = (pb < NE) ? pb : NE;
            int p = pa;
            for (; p + 8 <= pe; p += 8) {
                const float w0 = __ldcs(colE + (size_t)(p + 0) * stride);
                const float w1 = __ldcs(colE + (size_t)(p + 1) * stride);
                const float w2 = __ldcs(colE + (size_t)(p + 2) * stride);
                const float w3 = __ldcs(colE + (size_t)(p + 3) * stride);
                const float w4 = __ldcs(colE + (size_t)(p + 4) * stride);
                const float w5 = __ldcs(colE + (size_t)(p + 5) * stride);
                const float w6 = __ldcs(colE + (size_t)(p + 6) * stride);
                const float w7 = __ldcs(colE + (size_t)(p + 7) * stride);
                const int t = p - pa;
                acc = fmaf(w0, rs[t + 0], acc);
                acc = fmaf(w1, rs[t + 1], acc);
                acc = fmaf(w2, rs[t + 2], acc);
                acc = fmaf(w3, rs[t + 3], acc);
                acc = fmaf(w4, rs[t + 4], acc);
                acc = fmaf(w5, rs[t + 5], acc);
                acc = fmaf(w6, rs[t + 6], acc);
                acc = fmaf(w7, rs[t + 7], acc);
            }
            for (; p < pe; ++p)
                acc = fmaf(__ldcs(colE + (size_t)p * stride), rs[p - pa], acc);
        }

        // rows p in [max(pa, NE), pb) from the I-row matrix
        {
            const int p0 = (pa > NE) ? pa : NE;
            int p = p0;
            for (; p + 8 <= pb; p += 8) {
                const float w0 = __ldcs(colI + (size_t)(p - NE + 0) * stride);
                const float w1 = __ldcs(colI + (size_t)(p - NE + 1) * stride);
                const float w2 = __ldcs(colI + (size_t)(p - NE + 2) * stride);
                const float w3 = __ldcs(colI + (size_t)(p - NE + 3) * stride);
                const float w4 = __ldcs(colI + (size_t)(p - NE + 4) * stride);
                const float w5 = __ldcs(colI + (size_t)(p - NE + 5) * stride);
                const float w6 = __ldcs(colI + (size_t)(p - NE + 6) * stride);
                const float w7 = __ldcs(colI + (size_t)(p - NE + 7) * stride);
                const int t = p - pa;
                acc = fmaf(w0, rs[t + 0], acc);
                acc = fmaf(w1, rs[t + 1], acc);
                acc = fmaf(w2, rs[t + 2], acc);
                acc = fmaf(w3, rs[t + 3], acc);
                acc = fmaf(w4, rs[t + 4], acc);
                acc = fmaf(w5, rs[t + 5], acc);
                acc = fmaf(w6, rs[t + 6], acc);
                acc = fmaf(w7, rs[t + 7], acc);
            }
            for (; p < pb; ++p)
                acc = fmaf(__ldcs(colI + (size_t)(p - NE) * stride), rs[p - pa], acc);
        }

        g_partial[((size_t)ps * N_NET + n) * NU + q] = acc;
    }

#if __CUDA_ARCH__ >= 900
    cudaTriggerProgrammaticLaunchCompletion();
#endif
}

// ---------------------------------------------------------------------------
// Reduce 16 partials + unit_input (+inter for inhibitory) + epilogue.
// PDL-launched: prefetch primary-independent inputs, then grid-dep sync.
// ---------------------------------------------------------------------------
__global__ void __launch_bounds__(1024) reduce_kernel(
    const float* __restrict__ unit_input,
    const float* __restrict__ r,
    float* __restrict__ out)
{
    const int idx = blockIdx.x * 1024 + threadIdx.x;   // 0..65535
    const int n = idx >> 11;
    const int q = idx & 2047;

    const float ui = unit_input[idx];
    const float rv = r[idx];

#if __CUDA_ARCH__ >= 900
    cudaGridDependencySynchronize();
#endif

    float acc = 0.f;
    #pragma unroll
    for (int s = 0; s < P_SLICES; ++s)
        acc += g_partial[((size_t)s * N_NET + n) * NU + q];

    acc += ui;
    if (q >= NE) acc += g_inter[n * NI + (q - NE)];

    const float phi = fmaxf(acc, 0.f);
    out[idx] = rv + DT * ((phi - rv) / TAU);
}

extern "C" void kernel_launch(void* const* d_in, const int* in_sizes, int n_in,
                              void* d_out, int out_size)
{
    const float* unit_input = (const float*)d_in[0];
    const float* r          = (const float*)d_in[1];
    const float* W_ee       = (const float*)d_in[2];
    const float* W_ei       = (const float*)d_in[3];
    const float* W_ie       = (const float*)d_in[4];
    const float* W_ii       = (const float*)d_in[5];
    const float* W_inter    = (const float*)d_in[6];
    float* out = (float*)d_out;

    fused_kernel<<<TOTAL_BLOCKS, 128>>>(r, W_ee, W_ei, W_ie, W_ii, W_inter);

    cudaLaunchConfig_t cfg = {};
    cfg.gridDim  = dim3(64, 1, 1);
    cfg.blockDim = dim3(1024, 1, 1);
    cfg.dynamicSmemBytes = 0;
    cfg.stream = 0;
    cudaLaunchAttribute attrs[1];
    attrs[0].id = cudaLaunchAttributeProgrammaticStreamSerialization;
    attrs[0].val.programmaticStreamSerializationAllowed = 1;
    cfg.attrs = attrs;
    cfg.numAttrs = 1;
    cudaLaunchKernelEx(&cfg, reduce_kernel, unit_input, r, out);
}